// round 13
// baseline (speedup 1.0000x reference)
#include <cuda_runtime.h>
#include <math.h>
#include <stdint.h>

#define TOK    4096
#define DMODEL 1024
#define QKVN   3072
#define NHEAD  16
#define HDIM   64
#define LSEQ   2048
#define NBATCH 2

// ------------------------- static device scratch ---------------------------
__device__ float g_qkv[TOK * QKVN];
__device__ float g_headout[TOK * DMODEL];
__device__ float g_x32[TOK * DMODEL];
__device__ float g_wqkvT[QKVN * DMODEL];
__device__ float g_wprojT[DMODEL * DMODEL];

__device__ __forceinline__ float round_tf32f(float x) {
    uint32_t u;
    asm("cvt.rna.tf32.f32 %0, %1;" : "=r"(u) : "f"(x));
    return __uint_as_float(u);
}
__device__ __forceinline__ uint32_t tf32u(float x) {
    uint32_t u;
    asm("cvt.rna.tf32.f32 %0, %1;" : "=r"(u) : "f"(x));
    return u;
}
__device__ __forceinline__ void cp16(uint32_t s, const float* g) {
    asm volatile("cp.async.cg.shared.global [%0], [%1], 16;" :: "r"(s), "l"(g));
}
__device__ __forceinline__ void ldsm4(uint32_t& r0, uint32_t& r1, uint32_t& r2,
                                      uint32_t& r3, uint32_t addr) {
    asm volatile("ldmatrix.sync.aligned.m8n8.x4.shared.b16 {%0,%1,%2,%3}, [%4];"
                 : "=r"(r0), "=r"(r1), "=r"(r2), "=r"(r3) : "r"(addr));
}

#define MMA_TF32(C, A0, A1, A2, A3, B0, B1)                                    \
    asm volatile(                                                              \
        "mma.sync.aligned.m16n8k8.row.col.f32.tf32.tf32.f32 "                  \
        "{%0,%1,%2,%3}, {%4,%5,%6,%7}, {%8,%9}, {%0,%1,%2,%3};"                \
        : "+f"((C)[0]), "+f"((C)[1]), "+f"((C)[2]), "+f"((C)[3])               \
        : "r"(A0), "r"(A1), "r"(A2), "r"(A3), "r"(B0), "r"(B1))

// ---------------------------------------------------------------------------
// tf32 mma.sync GEMM: BK=32, 2-stage cp.async pipeline, ldmatrix frag loads.
// (unchanged — at the tf32 HMMA ceiling)
// ---------------------------------------------------------------------------
#define BK 32
#define LDT 36
#define SSTRF (2 * 128 * LDT)
#define GEMM_SMEM (2 * SSTRF * 4)

__global__ __launch_bounds__(256, 2) void tf32_mma_gemm(
    const float* __restrict__ A, const float* __restrict__ Bt,
    const float* __restrict__ bias, float* __restrict__ C,
    int N, int K)
{
    extern __shared__ float gs[];

    const int tid  = threadIdx.x;
    const int wid  = tid >> 5, lane = tid & 31;
    const int g    = lane >> 2, tg = lane & 3;
    const int wm   = (wid & 3) * 32;
    const int wn   = (wid >> 2) * 64;
    const int m0   = blockIdx.y * 128, n0 = blockIdx.x * 128;

    const uint32_t sbase = (uint32_t)__cvta_generic_to_shared(gs);
    const int q   = lane >> 3;
    const int lr8 = lane & 7;
    const uint32_t offA0 = (uint32_t)(((wm + (q & 1) * 8 + lr8) * LDT + (q >> 1) * 4) * 4);
    const uint32_t offA1 = offA0 + 16 * LDT * 4;
    const uint32_t offB  = (uint32_t)(((wn + (q >> 1) * 8 + lr8) * LDT + (q & 1) * 4) * 4)
                           + 128 * LDT * 4;

    float c[2][8][4];
#pragma unroll
    for (int i = 0; i < 2; i++)
#pragma unroll
        for (int j = 0; j < 8; j++)
#pragma unroll
            for (int r = 0; r < 4; r++) c[i][j][r] = 0.f;

    const int niter = K / BK;
    const int s0row = tid >> 3, s0c = (tid & 7) * 4;

#pragma unroll
    for (int i = 0; i < 4; i++) {
        const int row = s0row + i * 32;
        const uint32_t so = (uint32_t)((row * LDT + s0c) * 4);
        cp16(sbase + so, A + (size_t)(m0 + row) * K + s0c);
        cp16(sbase + so + 128 * LDT * 4, Bt + (size_t)(n0 + row) * K + s0c);
    }
    asm volatile("cp.async.commit_group;");

    for (int kt = 0; kt < niter; kt++) {
        asm volatile("cp.async.wait_group 0;");
        __syncthreads();

        if (kt + 1 < niter) {
            const uint32_t st = (uint32_t)(((kt + 1) & 1) * SSTRF * 4);
            const int kb = (kt + 1) * BK;
#pragma unroll
            for (int i = 0; i < 4; i++) {
                const int row = s0row + i * 32;
                const uint32_t so = st + (uint32_t)((row * LDT + s0c) * 4);
                cp16(sbase + so, A + (size_t)(m0 + row) * K + kb + s0c);
                cp16(sbase + so + 128 * LDT * 4, Bt + (size_t)(n0 + row) * K + kb + s0c);
            }
        }
        asm volatile("cp.async.commit_group;");

        const uint32_t sb = sbase + (uint32_t)((kt & 1) * SSTRF * 4);
#pragma unroll
        for (int kk = 0; kk < BK; kk += 8) {
            const uint32_t koff = kk * 4;
            uint32_t a[2][4], b[8][2];
            ldsm4(a[0][0], a[0][1], a[0][2], a[0][3], sb + offA0 + koff);
            ldsm4(a[1][0], a[1][1], a[1][2], a[1][3], sb + offA1 + koff);
#pragma unroll
            for (int jj = 0; jj < 4; jj++)
                ldsm4(b[2 * jj][0], b[2 * jj][1], b[2 * jj + 1][0], b[2 * jj + 1][1],
                      sb + offB + (uint32_t)(jj * 16 * LDT * 4) + koff);
#pragma unroll
            for (int i = 0; i < 2; i++)
#pragma unroll
                for (int j = 0; j < 8; j++)
                    MMA_TF32(c[i][j], a[i][0], a[i][1], a[i][2], a[i][3],
                             b[j][0], b[j][1]);
        }
    }

#pragma unroll
    for (int i = 0; i < 2; i++) {
        const int rowa = m0 + wm + i * 16 + g;
#pragma unroll
        for (int j = 0; j < 8; j++) {
            const int col = n0 + wn + j * 8 + 2 * tg;
            const float bx = bias[col], by = bias[col + 1];
            float2 v0 = make_float2(c[i][j][0] + bx, c[i][j][1] + by);
            float2 v1 = make_float2(c[i][j][2] + bx, c[i][j][3] + by);
            *(float2*)(C + (size_t)rowa * N + col)       = v0;
            *(float2*)(C + (size_t)(rowa + 8) * N + col) = v1;
        }
    }
}

// ---------------------------------------------------------------------------
// prep kernels
// ---------------------------------------------------------------------------
__global__ void round_copy(const float4* __restrict__ in, float4* __restrict__ out, int n4) {
    int i = blockIdx.x * 256 + threadIdx.x;
    if (i < n4) {
        float4 v = in[i];
        v.x = round_tf32f(v.x); v.y = round_tf32f(v.y);
        v.z = round_tf32f(v.z); v.w = round_tf32f(v.w);
        out[i] = v;
    }
}

__global__ __launch_bounds__(256) void transpose_round(
    const float* __restrict__ in, float* __restrict__ out, int K, int N)
{
    __shared__ float t[32][33];
    int bx = blockIdx.x * 32, by = blockIdx.y * 32;
    int x = threadIdx.x, y = threadIdx.y;
#pragma unroll
    for (int i = 0; i < 32; i += 8)
        t[y + i][x] = in[(size_t)(by + y + i) * N + bx + x];
    __syncthreads();
#pragma unroll
    for (int i = 0; i < 32; i += 8)
        out[(size_t)(bx + y + i) * K + by + x] = round_tf32f(t[x][y + i]);
}

// ---------------------------------------------------------------------------
// Sliding-window attention. Changes vs round-12 best:
//  * V staged in NATURAL [key][QK] layout (float4 stores, conflict-light;
//    the old transposed staging had 8-way bank conflicts on stores).
//    PV B-operand reads become SV[kc*QK + d] (same V[key][d] values).
//  * V0 staging issued before softmax — latency hidden under exp/sum/sync.
// ---------------------------------------------------------------------------
#define QK 68
#define PP 132
#define SM_SQ 0
#define SM_SK (128 * QK)
#define SM_SP 0
#define SM_SV (2 * 128 * QK)               // 17408
#define SM_SE (SM_SV + 128 * QK)           // 26112
#define ATT_FLOATS (SM_SE + 128 * QK)      // 34816
#define ATT_SMEM (ATT_FLOATS * 4)          // 139264 B

__global__ __launch_bounds__(512, 1) void attn_mma(
    const float* __restrict__ qkv,
    float* __restrict__ attn,
    float* __restrict__ head_out)
{
    extern __shared__ float sm[];
    float* SQ = sm + SM_SQ;
    float* SK = sm + SM_SK;
    float* SP = sm + SM_SP;
    float* SV = sm + SM_SV;
    float* SE = sm + SM_SE;

    const int qt = blockIdx.x, h = blockIdx.y, b = blockIdx.z;
    const int tid = threadIdx.x;
    const int w = tid >> 5, lane = tid & 31;
    const int wq = w & 7, wk = w >> 3;
    const int g = lane >> 2, tg = lane & 3;
    const int q0 = qt * 128;
    const int r1 = wq * 16 + g;
    const int r2 = r1 + 8;

    // ---- stage Q ----
    for (int idx = tid; idx < 2048; idx += 512) {
        int row = idx >> 4, d4 = (idx & 15) << 2;
        float4 v = *(const float4*)(qkv + (size_t)(b * LSEQ + q0 + row) * QKVN + h * HDIM + d4);
        v.x = round_tf32f(v.x * 0.125f);
        v.y = round_tf32f(v.y * 0.125f);
        v.z = round_tf32f(v.z * 0.125f);
        v.w = round_tf32f(v.w * 0.125f);
        *(float4*)&SQ[row * QK + d4] = v;
    }

    float p[2][8][4];
#pragma unroll
    for (int c = 0; c < 2; c++)
#pragma unroll
        for (int j = 0; j < 8; j++)
#pragma unroll
            for (int r = 0; r < 4; r++) p[c][j][r] = 0.f;

    // ---- S = Q K^T per chunk ----
#pragma unroll
    for (int c = 0; c < 2; c++) {
        const int kb = q0 + (c - 1) * 128;
        __syncthreads();
        for (int idx = tid; idx < 2048; idx += 512) {
            int row = idx >> 4, d4 = (idx & 15) << 2;
            int kk = kb + row;
            float4 v = make_float4(0.f, 0.f, 0.f, 0.f);
            if (kk >= 0)
                v = *(const float4*)(qkv + (size_t)(b * LSEQ + kk) * QKVN + DMODEL + h * HDIM + d4);
            v.x = round_tf32f(v.x); v.y = round_tf32f(v.y);
            v.z = round_tf32f(v.z); v.w = round_tf32f(v.w);
            *(float4*)&SK[row * QK + d4] = v;
        }
        __syncthreads();

#pragma unroll
        for (int kkb = 0; kkb < 8; kkb++) {
            const int kc = kkb * 8 + tg;
            uint32_t a0 = __float_as_uint(SQ[r1 * QK + kc]);
            uint32_t a1 = __float_as_uint(SQ[r2 * QK + kc]);
            uint32_t a2 = __float_as_uint(SQ[r1 * QK + kc + 4]);
            uint32_t a3 = __float_as_uint(SQ[r2 * QK + kc + 4]);
#pragma unroll
            for (int j = 0; j < 8; j++) {
                const int col = wk * 64 + j * 8 + g;
                uint32_t b0 = __float_as_uint(SK[col * QK + kc]);
                uint32_t b1 = __float_as_uint(SK[col * QK + kc + 4]);
                MMA_TF32(p[c][j], a0, a1, a2, a3, b0, b1);
            }
        }
    }

    // ---- stage V chunk0 early (SV is a private buffer; latency hides under
    //      softmax / sums / SE sync below) ----
    {
        const int kb = q0 - 128;
        for (int idx = tid; idx < 2048; idx += 512) {
            int key = idx >> 4, d4 = (idx & 15) << 2;
            int kk = kb + key;
            float4 v = make_float4(0.f, 0.f, 0.f, 0.f);
            if (kk >= 0)
                v = *(const float4*)(qkv + (size_t)(b * LSEQ + kk) * QKVN + 2 * DMODEL + h * HDIM + d4);
            v.x = round_tf32f(v.x); v.y = round_tf32f(v.y);
            v.z = round_tf32f(v.z); v.w = round_tf32f(v.w);
            *(float4*)&SV[key * QK + d4] = v;
        }
    }

    // ---- mask + exp + row sums ----
    float s1 = 0.f, s2 = 0.f;
#pragma unroll
    for (int c = 0; c < 2; c++)
#pragma unroll
        for (int j = 0; j < 8; j++)
#pragma unroll
            for (int e = 0; e < 2; e++) {
                int colc = wk * 64 + j * 8 + 2 * tg + e;
                int key = q0 + (c - 1) * 128 + colc;
                bool v1 = (c == 0) ? (colc > r1 && key >= 0) : (colc <= r1);
                bool v2 = (c == 0) ? (colc > r2 && key >= 0) : (colc <= r2);
                float e1 = v1 ? __expf(p[c][j][e])     : 0.f;
                float e2 = v2 ? __expf(p[c][j][2 + e]) : 0.f;
                p[c][j][e]     = e1;
                p[c][j][2 + e] = e2;
                s1 += e1;
                s2 += e2;
            }
    s1 += __shfl_xor_sync(0xffffffffu, s1, 1);
    s1 += __shfl_xor_sync(0xffffffffu, s1, 2);
    s2 += __shfl_xor_sync(0xffffffffu, s2, 1);
    s2 += __shfl_xor_sync(0xffffffffu, s2, 2);
    if (tg == 0) {
        SE[wk * 128 + r1] = s1;
        SE[wk * 128 + r2] = s2;
    }
    __syncthreads();   // SE visible; also: all warps past S phase (SQ/SK dead)
    const float i1 = 1.f / (SE[r1] + SE[128 + r1]);
    const float i2 = 1.f / (SE[r2] + SE[128 + r2]);

    float o[8][4];
#pragma unroll
    for (int j = 0; j < 8; j++)
#pragma unroll
        for (int r = 0; r < 4; r++) o[j][r] = 0.f;

    float* abase = attn + ((size_t)(b * NHEAD + h) * LSEQ + q0) * (size_t)LSEQ;

#pragma unroll
    for (int c = 0; c < 2; c++) {
        // park normalized P for this chunk (SP overlays SQ+SK, dead after SE sync)
#pragma unroll
        for (int j = 0; j < 8; j++) {
            const int colc = wk * 64 + j * 8 + 2 * tg;
            *(float2*)&SP[r1 * PP + colc] = make_float2(p[c][j][0] * i1, p[c][j][1] * i1);
            *(float2*)&SP[r2 * PP + colc] = make_float2(p[c][j][2] * i2, p[c][j][3] * i2);
        }

        // stage V for chunk 1 (chunk 0's V was staged before softmax)
        if (c == 1) {
            for (int idx = tid; idx < 2048; idx += 512) {
                int key = idx >> 4, d4 = (idx & 15) << 2;
                float4 v = *(const float4*)(qkv + (size_t)(b * LSEQ + q0 + key) * QKVN
                                            + 2 * DMODEL + h * HDIM + d4);
                v.x = round_tf32f(v.x); v.y = round_tf32f(v.y);
                v.z = round_tf32f(v.z); v.w = round_tf32f(v.w);
                *(float4*)&SV[key * QK + d4] = v;
            }
        }
        __syncthreads();   // park + V stage visible

        // coalesced slab write (streaming stores)
        if (c == 0) {
            const int n4 = q0 >> 2;
            const int rel0 = q0 - 128;
            for (int idx = tid; idx < 128 * n4; idx += 512) {
                int row = idx / n4;
                int col = (idx - row * n4) << 2;
                int rel = col - rel0;
                float4 v = make_float4(0.f, 0.f, 0.f, 0.f);
                if (rel >= 0) v = *(const float4*)&SP[row * PP + rel];
                __stcs((float4*)(abase + (size_t)row * LSEQ + col), v);
            }
        } else {
            const int n4 = (LSEQ - q0) >> 2;
            for (int idx = tid; idx < 128 * n4; idx += 512) {
                int row = idx / n4;
                int rel = (idx - row * n4) << 2;
                float4 v = make_float4(0.f, 0.f, 0.f, 0.f);
                if (rel < 128) v = *(const float4*)&SP[row * PP + rel];
                __stcs((float4*)(abase + (size_t)row * LSEQ + q0 + rel), v);
            }
        }

        // PV partial: keys [wk*64, wk*64+64); V in natural [key][QK] layout
#pragma unroll
        for (int kk = 0; kk < 8; kk++) {
            const int kc = wk * 64 + kk * 8 + tg;
            uint32_t a0 = tf32u(SP[r1 * PP + kc]);
            uint32_t a1 = tf32u(SP[r2 * PP + kc]);
            uint32_t a2 = tf32u(SP[r1 * PP + kc + 4]);
            uint32_t a3 = tf32u(SP[r2 * PP + kc + 4]);
#pragma unroll
            for (int j2 = 0; j2 < 8; j2++) {
                const int d = j2 * 8 + g;
                uint32_t b0 = __float_as_uint(SV[kc * QK + d]);
                uint32_t b1 = __float_as_uint(SV[(kc + 4) * QK + d]);
                MMA_TF32(o[j2], a0, a1, a2, a3, b0, b1);
            }
        }

        if (c == 0) __syncthreads();   // SP/SV reads done before re-park/re-stage
    }

    // ---- O exchange between wk halves; wk=1 writes head_out ----
    __syncthreads();
    if (wk == 0) {
#pragma unroll
        for (int j2 = 0; j2 < 8; j2++) {
            const int col = j2 * 8 + 2 * tg;
            *(float2*)&SE[r1 * QK + col] = make_float2(o[j2][0], o[j2][1]);
            *(float2*)&SE[r2 * QK + col] = make_float2(o[j2][2], o[j2][3]);
        }
    }
    __syncthreads();
    if (wk == 1) {
#pragma unroll
        for (int j2 = 0; j2 < 8; j2++) {
            const int col = j2 * 8 + 2 * tg;
            float2 e1 = *(const float2*)&SE[r1 * QK + col];
            float2 e2 = *(const float2*)&SE[r2 * QK + col];
            float2 v1 = make_float2(round_tf32f(o[j2][0] + e1.x), round_tf32f(o[j2][1] + e1.y));
            float2 v2 = make_float2(round_tf32f(o[j2][2] + e2.x), round_tf32f(o[j2][3] + e2.y));
            *(float2*)(head_out + (size_t)(b * LSEQ + q0 + r1) * DMODEL + h * HDIM + col) = v1;
            *(float2*)(head_out + (size_t)(b * LSEQ + q0 + r2) * DMODEL + h * HDIM + col) = v2;
        }
    }
}

// ---------------------------------------------------------------------------
extern "C" void kernel_launch(void* const* d_in, const int* in_sizes, int n_in,
                              void* d_out, int out_size)
{
    const float* x      = (const float*)d_in[0];
    const float* W_qkv  = (const float*)d_in[1];
    const float* b_qkv  = (const float*)d_in[2];
    const float* W_proj = (const float*)d_in[3];
    const float* b_proj = (const float*)d_in[4];
    (void)in_sizes; (void)n_in; (void)out_size;

    float* out  = (float*)d_out;
    float* attn = out + (size_t)NBATCH * LSEQ * DMODEL;

    float *qkv = nullptr, *hout = nullptr, *x32 = nullptr,
          *wqkvT = nullptr, *wprojT = nullptr;
    cudaGetSymbolAddress((void**)&qkv,    g_qkv);
    cudaGetSymbolAddress((void**)&hout,   g_headout);
    cudaGetSymbolAddress((void**)&x32,    g_x32);
    cudaGetSymbolAddress((void**)&wqkvT,  g_wqkvT);
    cudaGetSymbolAddress((void**)&wprojT, g_wprojT);

    cudaFuncSetAttribute(attn_mma, cudaFuncAttributeMaxDynamicSharedMemorySize, ATT_SMEM);
    cudaFuncSetAttribute(tf32_mma_gemm, cudaFuncAttributeMaxDynamicSharedMemorySize, GEMM_SMEM);

    round_copy<<<(TOK * DMODEL / 4 + 255) / 256, 256>>>((const float4*)x, (float4*)x32, TOK * DMODEL / 4);
    transpose_round<<<dim3(QKVN / 32, DMODEL / 32), dim3(32, 8)>>>(W_qkv, wqkvT, DMODEL, QKVN);
    transpose_round<<<dim3(DMODEL / 32, DMODEL / 32), dim3(32, 8)>>>(W_proj, wprojT, DMODEL, DMODEL);

    tf32_mma_gemm<<<dim3(QKVN / 128, TOK / 128), 256, GEMM_SMEM>>>(
        x32, wqkvT, b_qkv, qkv, QKVN, DMODEL);

    attn_mma<<<dim3(LSEQ / 128, NHEAD, NBATCH), 512, ATT_SMEM>>>(qkv, attn, hout);

    tf32_mma_gemm<<<dim3(DMODEL / 128, TOK / 128), 256, GEMM_SMEM>>>(
        hout, wprojT, b_proj, out, DMODEL, DMODEL);
}

// round 14
// speedup vs baseline: 1.0837x; 1.0837x over previous
#include <cuda_runtime.h>
#include <math.h>
#include <stdint.h>

#define TOK    4096
#define DMODEL 1024
#define QKVN   3072
#define NHEAD  16
#define HDIM   64
#define LSEQ   2048
#define NBATCH 2

// ------------------------- static device scratch ---------------------------
__device__ float g_qkv[TOK * QKVN];
__device__ float g_headout[TOK * DMODEL];
__device__ float g_x32[TOK * DMODEL];
__device__ float g_wqkvT[QKVN * DMODEL];
__device__ float g_wprojT[DMODEL * DMODEL];

__device__ __forceinline__ float round_tf32f(float x) {
    uint32_t u;
    asm("cvt.rna.tf32.f32 %0, %1;" : "=r"(u) : "f"(x));
    return __uint_as_float(u);
}
__device__ __forceinline__ uint32_t tf32u(float x) {
    uint32_t u;
    asm("cvt.rna.tf32.f32 %0, %1;" : "=r"(u) : "f"(x));
    return u;
}
__device__ __forceinline__ void cp16(uint32_t s, const float* g) {
    asm volatile("cp.async.cg.shared.global [%0], [%1], 16;" :: "r"(s), "l"(g));
}
__device__ __forceinline__ void ldsm4(uint32_t& r0, uint32_t& r1, uint32_t& r2,
                                      uint32_t& r3, uint32_t addr) {
    asm volatile("ldmatrix.sync.aligned.m8n8.x4.shared.b16 {%0,%1,%2,%3}, [%4];"
                 : "=r"(r0), "=r"(r1), "=r"(r2), "=r"(r3) : "r"(addr));
}

#define MMA_TF32(C, A0, A1, A2, A3, B0, B1)                                    \
    asm volatile(                                                              \
        "mma.sync.aligned.m16n8k8.row.col.f32.tf32.tf32.f32 "                  \
        "{%0,%1,%2,%3}, {%4,%5,%6,%7}, {%8,%9}, {%0,%1,%2,%3};"                \
        : "+f"((C)[0]), "+f"((C)[1]), "+f"((C)[2]), "+f"((C)[3])               \
        : "r"(A0), "r"(A1), "r"(A2), "r"(A3), "r"(B0), "r"(B1))

// ---------------------------------------------------------------------------
// tf32 mma.sync GEMM: BK=32, 2-stage cp.async pipeline, ldmatrix frag loads.
// (unchanged — at the tf32 HMMA ceiling)
// ---------------------------------------------------------------------------
#define BK 32
#define LDT 36
#define SSTRF (2 * 128 * LDT)
#define GEMM_SMEM (2 * SSTRF * 4)

__global__ __launch_bounds__(256, 2) void tf32_mma_gemm(
    const float* __restrict__ A, const float* __restrict__ Bt,
    const float* __restrict__ bias, float* __restrict__ C,
    int N, int K)
{
    extern __shared__ float gs[];

    const int tid  = threadIdx.x;
    const int wid  = tid >> 5, lane = tid & 31;
    const int g    = lane >> 2, tg = lane & 3;
    const int wm   = (wid & 3) * 32;
    const int wn   = (wid >> 2) * 64;
    const int m0   = blockIdx.y * 128, n0 = blockIdx.x * 128;

    const uint32_t sbase = (uint32_t)__cvta_generic_to_shared(gs);
    const int q   = lane >> 3;
    const int lr8 = lane & 7;
    const uint32_t offA0 = (uint32_t)(((wm + (q & 1) * 8 + lr8) * LDT + (q >> 1) * 4) * 4);
    const uint32_t offA1 = offA0 + 16 * LDT * 4;
    const uint32_t offB  = (uint32_t)(((wn + (q >> 1) * 8 + lr8) * LDT + (q & 1) * 4) * 4)
                           + 128 * LDT * 4;

    float c[2][8][4];
#pragma unroll
    for (int i = 0; i < 2; i++)
#pragma unroll
        for (int j = 0; j < 8; j++)
#pragma unroll
            for (int r = 0; r < 4; r++) c[i][j][r] = 0.f;

    const int niter = K / BK;
    const int s0row = tid >> 3, s0c = (tid & 7) * 4;

#pragma unroll
    for (int i = 0; i < 4; i++) {
        const int row = s0row + i * 32;
        const uint32_t so = (uint32_t)((row * LDT + s0c) * 4);
        cp16(sbase + so, A + (size_t)(m0 + row) * K + s0c);
        cp16(sbase + so + 128 * LDT * 4, Bt + (size_t)(n0 + row) * K + s0c);
    }
    asm volatile("cp.async.commit_group;");

    for (int kt = 0; kt < niter; kt++) {
        asm volatile("cp.async.wait_group 0;");
        __syncthreads();

        if (kt + 1 < niter) {
            const uint32_t st = (uint32_t)(((kt + 1) & 1) * SSTRF * 4);
            const int kb = (kt + 1) * BK;
#pragma unroll
            for (int i = 0; i < 4; i++) {
                const int row = s0row + i * 32;
                const uint32_t so = st + (uint32_t)((row * LDT + s0c) * 4);
                cp16(sbase + so, A + (size_t)(m0 + row) * K + kb + s0c);
                cp16(sbase + so + 128 * LDT * 4, Bt + (size_t)(n0 + row) * K + kb + s0c);
            }
        }
        asm volatile("cp.async.commit_group;");

        const uint32_t sb = sbase + (uint32_t)((kt & 1) * SSTRF * 4);
#pragma unroll
        for (int kk = 0; kk < BK; kk += 8) {
            const uint32_t koff = kk * 4;
            uint32_t a[2][4], b[8][2];
            ldsm4(a[0][0], a[0][1], a[0][2], a[0][3], sb + offA0 + koff);
            ldsm4(a[1][0], a[1][1], a[1][2], a[1][3], sb + offA1 + koff);
#pragma unroll
            for (int jj = 0; jj < 4; jj++)
                ldsm4(b[2 * jj][0], b[2 * jj][1], b[2 * jj + 1][0], b[2 * jj + 1][1],
                      sb + offB + (uint32_t)(jj * 16 * LDT * 4) + koff);
#pragma unroll
            for (int i = 0; i < 2; i++)
#pragma unroll
                for (int j = 0; j < 8; j++)
                    MMA_TF32(c[i][j], a[i][0], a[i][1], a[i][2], a[i][3],
                             b[j][0], b[j][1]);
        }
    }

#pragma unroll
    for (int i = 0; i < 2; i++) {
        const int rowa = m0 + wm + i * 16 + g;
#pragma unroll
        for (int j = 0; j < 8; j++) {
            const int col = n0 + wn + j * 8 + 2 * tg;
            const float bx = bias[col], by = bias[col + 1];
            float2 v0 = make_float2(c[i][j][0] + bx, c[i][j][1] + by);
            float2 v1 = make_float2(c[i][j][2] + bx, c[i][j][3] + by);
            *(float2*)(C + (size_t)rowa * N + col)       = v0;
            *(float2*)(C + (size_t)(rowa + 8) * N + col) = v1;
        }
    }
}

// ---------------------------------------------------------------------------
// prep kernels
// ---------------------------------------------------------------------------
__global__ void round_copy(const float4* __restrict__ in, float4* __restrict__ out, int n4) {
    int i = blockIdx.x * 256 + threadIdx.x;
    if (i < n4) {
        float4 v = in[i];
        v.x = round_tf32f(v.x); v.y = round_tf32f(v.y);
        v.z = round_tf32f(v.z); v.w = round_tf32f(v.w);
        out[i] = v;
    }
}

__global__ __launch_bounds__(256) void transpose_round(
    const float* __restrict__ in, float* __restrict__ out, int K, int N)
{
    __shared__ float t[32][33];
    int bx = blockIdx.x * 32, by = blockIdx.y * 32;
    int x = threadIdx.x, y = threadIdx.y;
#pragma unroll
    for (int i = 0; i < 32; i += 8)
        t[y + i][x] = in[(size_t)(by + y + i) * N + bx + x];
    __syncthreads();
#pragma unroll
    for (int i = 0; i < 32; i += 8)
        out[(size_t)(bx + y + i) * K + by + x] = round_tf32f(t[x][y + i]);
}

// ---------------------------------------------------------------------------
// Sliding-window attention v3: 64 queries/block, 256 threads (8 warps =
// 4 query-stripes x 2 key-halves), smem 86.5KB + regs<=128 -> 2 CTAs/SM so
// the 536MB write phases of one CTA overlap the compute phases of the other.
// Round-12 math/scheduling preserved (V transposed staging, in-loop stage).
// ---------------------------------------------------------------------------
#define QK 68
#define PP 132
#define SM_SQ 0
#define SM_SK (64 * QK)                    // 4352
#define SM_SP 0                             // 64*132=8448 overlays SQ+SK (13056)
#define SM_SV (64 * QK + 128 * QK)          // 13056 ; V^T [64][PP] = 8448
#define SM_SE SM_SV                         // O-exchange overlays SV (4352<=8448)
#define SM_SUM (SM_SV + 64 * PP)            // 21504 ; 128 floats
#define ATT_FLOATS (SM_SUM + 128)           // 21632
#define ATT_SMEM (ATT_FLOATS * 4)           // 86528 B

__global__ __launch_bounds__(256, 2) void attn_mma(
    const float* __restrict__ qkv,
    float* __restrict__ attn,
    float* __restrict__ head_out)
{
    extern __shared__ float sm[];
    float* SQ  = sm + SM_SQ;
    float* SK  = sm + SM_SK;
    float* SP  = sm + SM_SP;
    float* SV  = sm + SM_SV;
    float* SE  = sm + SM_SE;
    float* SSUM = sm + SM_SUM;

    const int qt = blockIdx.x, h = blockIdx.y, b = blockIdx.z;
    const int tid = threadIdx.x;
    const int w = tid >> 5, lane = tid & 31;
    const int wq = w & 3, wk = w >> 2;
    const int g = lane >> 2, tg = lane & 3;
    const int q0 = qt * 64;
    const int r1 = wq * 16 + g;      // local query rows 0..63
    const int r2 = r1 + 8;

    // ---- stage Q (64 rows) ----
    for (int idx = tid; idx < 1024; idx += 256) {
        int row = idx >> 4, d4 = (idx & 15) << 2;
        float4 v = *(const float4*)(qkv + (size_t)(b * LSEQ + q0 + row) * QKVN + h * HDIM + d4);
        v.x = round_tf32f(v.x * 0.125f);
        v.y = round_tf32f(v.y * 0.125f);
        v.z = round_tf32f(v.z * 0.125f);
        v.w = round_tf32f(v.w * 0.125f);
        *(float4*)&SQ[row * QK + d4] = v;
    }

    float p[2][8][4];
#pragma unroll
    for (int c = 0; c < 2; c++)
#pragma unroll
        for (int j = 0; j < 8; j++)
#pragma unroll
            for (int r = 0; r < 4; r++) p[c][j][r] = 0.f;

    // ---- S = Q K^T per 128-key chunk (chunk1 upper 64 keys are waste) ----
#pragma unroll
    for (int c = 0; c < 2; c++) {
        const int kb = q0 + (c - 1) * 128;
        __syncthreads();
        for (int idx = tid; idx < 2048; idx += 256) {
            int row = idx >> 4, d4 = (idx & 15) << 2;
            int kk = kb + row;
            float4 v = make_float4(0.f, 0.f, 0.f, 0.f);
            if (kk >= 0 && kk < LSEQ)
                v = *(const float4*)(qkv + (size_t)(b * LSEQ + kk) * QKVN + DMODEL + h * HDIM + d4);
            v.x = round_tf32f(v.x); v.y = round_tf32f(v.y);
            v.z = round_tf32f(v.z); v.w = round_tf32f(v.w);
            *(float4*)&SK[row * QK + d4] = v;
        }
        __syncthreads();

#pragma unroll
        for (int kkb = 0; kkb < 8; kkb++) {
            const int kc = kkb * 8 + tg;
            uint32_t a0 = __float_as_uint(SQ[r1 * QK + kc]);
            uint32_t a1 = __float_as_uint(SQ[r2 * QK + kc]);
            uint32_t a2 = __float_as_uint(SQ[r1 * QK + kc + 4]);
            uint32_t a3 = __float_as_uint(SQ[r2 * QK + kc + 4]);
#pragma unroll
            for (int j = 0; j < 8; j++) {
                const int col = wk * 64 + j * 8 + g;
                uint32_t b0 = __float_as_uint(SK[col * QK + kc]);
                uint32_t b1 = __float_as_uint(SK[col * QK + kc + 4]);
                MMA_TF32(p[c][j], a0, a1, a2, a3, b0, b1);
            }
        }
    }

    // ---- mask + exp + row sums ----
    float s1 = 0.f, s2 = 0.f;
#pragma unroll
    for (int c = 0; c < 2; c++)
#pragma unroll
        for (int j = 0; j < 8; j++)
#pragma unroll
            for (int e = 0; e < 2; e++) {
                int colc = wk * 64 + j * 8 + 2 * tg + e;
                int key = q0 + (c - 1) * 128 + colc;
                bool v1 = (c == 0) ? (colc > r1 && key >= 0) : (colc <= r1);
                bool v2 = (c == 0) ? (colc > r2 && key >= 0) : (colc <= r2);
                float e1 = v1 ? __expf(p[c][j][e])     : 0.f;
                float e2 = v2 ? __expf(p[c][j][2 + e]) : 0.f;
                p[c][j][e]     = e1;
                p[c][j][2 + e] = e2;
                s1 += e1;
                s2 += e2;
            }
    s1 += __shfl_xor_sync(0xffffffffu, s1, 1);
    s1 += __shfl_xor_sync(0xffffffffu, s1, 2);
    s2 += __shfl_xor_sync(0xffffffffu, s2, 1);
    s2 += __shfl_xor_sync(0xffffffffu, s2, 2);
    if (tg == 0) {
        SSUM[wk * 64 + r1] = s1;
        SSUM[wk * 64 + r2] = s2;
    }
    __syncthreads();   // sums visible; all warps past S phase (SQ/SK dead)
    const float i1 = 1.f / (SSUM[r1] + SSUM[64 + r1]);
    const float i2 = 1.f / (SSUM[r2] + SSUM[64 + r2]);

    float o[8][4];
#pragma unroll
    for (int j = 0; j < 8; j++)
#pragma unroll
        for (int r = 0; r < 4; r++) o[j][r] = 0.f;

    float* abase = attn + ((size_t)(b * NHEAD + h) * LSEQ + q0) * (size_t)LSEQ;

#pragma unroll
    for (int c = 0; c < 2; c++) {
        const int kb = q0 + (c - 1) * 128;
        __syncthreads();

        // park normalized P (masked entries exact zeros)
#pragma unroll
        for (int j = 0; j < 8; j++) {
            const int colc = wk * 64 + j * 8 + 2 * tg;
            *(float2*)&SP[r1 * PP + colc] = make_float2(p[c][j][0] * i1, p[c][j][1] * i1);
            *(float2*)&SP[r2 * PP + colc] = make_float2(p[c][j][2] * i2, p[c][j][3] * i2);
        }

        // stage V^T [d][key] (round-12 layout; clamped key range)
        for (int idx = tid; idx < 2048; idx += 256) {
            int key = idx >> 4, d4 = (idx & 15) << 2;
            int kk = kb + key;
            float4 v = make_float4(0.f, 0.f, 0.f, 0.f);
            if (kk >= 0 && kk < LSEQ)
                v = *(const float4*)(qkv + (size_t)(b * LSEQ + kk) * QKVN + 2 * DMODEL + h * HDIM + d4);
            SV[(d4 + 0) * PP + key] = round_tf32f(v.x);
            SV[(d4 + 1) * PP + key] = round_tf32f(v.y);
            SV[(d4 + 2) * PP + key] = round_tf32f(v.z);
            SV[(d4 + 3) * PP + key] = round_tf32f(v.w);
        }
        __syncthreads();

        // coalesced slab write (streaming stores; 64 rows)
        if (c == 0) {
            const int n4 = q0 >> 2;
            const int rel0 = q0 - 128;
            for (int idx = tid; idx < 64 * n4; idx += 256) {
                int row = idx / n4;
                int col = (idx - row * n4) << 2;
                int rel = col - rel0;
                float4 v = make_float4(0.f, 0.f, 0.f, 0.f);
                if (rel >= 0) v = *(const float4*)&SP[row * PP + rel];
                __stcs((float4*)(abase + (size_t)row * LSEQ + col), v);
            }
        } else {
            const int n4 = (LSEQ - q0) >> 2;
            for (int idx = tid; idx < 64 * n4; idx += 256) {
                int row = idx / n4;
                int rel = (idx - row * n4) << 2;
                float4 v = make_float4(0.f, 0.f, 0.f, 0.f);
                if (rel < 128) v = *(const float4*)&SP[row * PP + rel];
                __stcs((float4*)(abase + (size_t)row * LSEQ + q0 + rel), v);
            }
        }

        // PV partial: keys [wk*64, wk*64+64)
#pragma unroll
        for (int kk = 0; kk < 8; kk++) {
            const int kc = wk * 64 + kk * 8 + tg;
            uint32_t a0 = tf32u(SP[r1 * PP + kc]);
            uint32_t a1 = tf32u(SP[r2 * PP + kc]);
            uint32_t a2 = tf32u(SP[r1 * PP + kc + 4]);
            uint32_t a3 = tf32u(SP[r2 * PP + kc + 4]);
#pragma unroll
            for (int j2 = 0; j2 < 8; j2++) {
                const int d = j2 * 8 + g;
                uint32_t b0 = __float_as_uint(SV[d * PP + kc]);
                uint32_t b1 = __float_as_uint(SV[d * PP + kc + 4]);
                MMA_TF32(o[j2], a0, a1, a2, a3, b0, b1);
            }
        }
    }

    // ---- O exchange between wk halves (SE overlays SV; PV done) ----
    __syncthreads();
    if (wk == 0) {
#pragma unroll
        for (int j2 = 0; j2 < 8; j2++) {
            const int col = j2 * 8 + 2 * tg;
            *(float2*)&SE[r1 * QK + col] = make_float2(o[j2][0], o[j2][1]);
            *(float2*)&SE[r2 * QK + col] = make_float2(o[j2][2], o[j2][3]);
        }
    }
    __syncthreads();
    if (wk == 1) {
#pragma unroll
        for (int j2 = 0; j2 < 8; j2++) {
            const int col = j2 * 8 + 2 * tg;
            float2 e1 = *(const float2*)&SE[r1 * QK + col];
            float2 e2 = *(const float2*)&SE[r2 * QK + col];
            float2 v1 = make_float2(round_tf32f(o[j2][0] + e1.x), round_tf32f(o[j2][1] + e1.y));
            float2 v2 = make_float2(round_tf32f(o[j2][2] + e2.x), round_tf32f(o[j2][3] + e2.y));
            *(float2*)(head_out + (size_t)(b * LSEQ + q0 + r1) * DMODEL + h * HDIM + col) = v1;
            *(float2*)(head_out + (size_t)(b * LSEQ + q0 + r2) * DMODEL + h * HDIM + col) = v2;
        }
    }
}

// ---------------------------------------------------------------------------
extern "C" void kernel_launch(void* const* d_in, const int* in_sizes, int n_in,
                              void* d_out, int out_size)
{
    const float* x      = (const float*)d_in[0];
    const float* W_qkv  = (const float*)d_in[1];
    const float* b_qkv  = (const float*)d_in[2];
    const float* W_proj = (const float*)d_in[3];
    const float* b_proj = (const float*)d_in[4];
    (void)in_sizes; (void)n_in; (void)out_size;

    float* out  = (float*)d_out;
    float* attn = out + (size_t)NBATCH * LSEQ * DMODEL;

    float *qkv = nullptr, *hout = nullptr, *x32 = nullptr,
          *wqkvT = nullptr, *wprojT = nullptr;
    cudaGetSymbolAddress((void**)&qkv,    g_qkv);
    cudaGetSymbolAddress((void**)&hout,   g_headout);
    cudaGetSymbolAddress((void**)&x32,    g_x32);
    cudaGetSymbolAddress((void**)&wqkvT,  g_wqkvT);
    cudaGetSymbolAddress((void**)&wprojT, g_wprojT);

    cudaFuncSetAttribute(attn_mma, cudaFuncAttributeMaxDynamicSharedMemorySize, ATT_SMEM);
    cudaFuncSetAttribute(tf32_mma_gemm, cudaFuncAttributeMaxDynamicSharedMemorySize, GEMM_SMEM);

    round_copy<<<(TOK * DMODEL / 4 + 255) / 256, 256>>>((const float4*)x, (float4*)x32, TOK * DMODEL / 4);
    transpose_round<<<dim3(QKVN / 32, DMODEL / 32), dim3(32, 8)>>>(W_qkv, wqkvT, DMODEL, QKVN);
    transpose_round<<<dim3(DMODEL / 32, DMODEL / 32), dim3(32, 8)>>>(W_proj, wprojT, DMODEL, DMODEL);

    tf32_mma_gemm<<<dim3(QKVN / 128, TOK / 128), 256, GEMM_SMEM>>>(
        x32, wqkvT, b_qkv, qkv, QKVN, DMODEL);

    attn_mma<<<dim3(LSEQ / 64, NHEAD, NBATCH), 256, ATT_SMEM>>>(qkv, attn, hout);

    tf32_mma_gemm<<<dim3(DMODEL / 128, TOK / 128), 256, GEMM_SMEM>>>(
        hout, wprojT, b_proj, out, DMODEL, DMODEL);
}